// round 3
// baseline (speedup 1.0000x reference)
#include <cuda_runtime.h>
#include <cuda_bf16.h>
#include <math.h>

#define C_DIM 40
#define TPR 8              // threads per row
#define ROWS_PER_WARP 4
#define THREADS 256
#define ROWS_PER_BLOCK (THREADS / TPR)   // 32

__global__ void init_out_kernel(float* out) {
    out[0] = 0.0f;
}

__global__ __launch_bounds__(THREADS) void hier_loss_kernel(
    const float* __restrict__ logits,   // [B, 40]
    const int*   __restrict__ labels,   // [B]
    const float* __restrict__ dis,      // [40, 40]
    float* __restrict__ out,            // out[0]=loss, out[1..B]=distance_factor
    int B)
{
    const int tid  = threadIdx.x;
    const int lane = tid & 31;
    const int warp = tid >> 5;
    const int sub  = lane & (TPR - 1);           // 0..7 within row-group
    const int rowInWarp = lane >> 3;             // 0..3

    const int row = (blockIdx.x * (THREADS >> 5) + warp) * ROWS_PER_WARP + rowInWarp;

    float contrib = 0.0f;

    if (row < B) {
        const float* base = logits + (long long)row * C_DIM;

        // Each thread owns 5 elements: indices sub*4+0..3 and 32+sub.
        float4 q = __ldg(reinterpret_cast<const float4*>(base) + sub);  // floats [4*sub .. 4*sub+3]
        float  t = __ldg(base + 32 + sub);                              // float [32+sub]

        float v[5] = {q.x, q.y, q.z, q.w, t};
        int  idx[5] = {4 * sub, 4 * sub + 1, 4 * sub + 2, 4 * sub + 3, 32 + sub};

        // --- local max + argmax (first occurrence) ---
        float mx = v[0]; int am = idx[0];
        #pragma unroll
        for (int i = 1; i < 5; i++) {
            if (v[i] > mx) { mx = v[i]; am = idx[i]; }
        }
        // --- 8-lane butterfly reduce max/argmax, tie -> smaller index ---
        #pragma unroll
        for (int off = 1; off < TPR; off <<= 1) {
            float omx = __shfl_xor_sync(0xFFFFFFFFu, mx, off);
            int   oam = __shfl_xor_sync(0xFFFFFFFFu, am, off);
            if (omx > mx || (omx == mx && oam < am)) { mx = omx; am = oam; }
        }

        // --- label (broadcast load, all 8 lanes same addr) ---
        int lbl = __ldg(labels + row);

        // --- sum exp(v - mx) and x[label] selection ---
        float s = 0.0f;
        float xl = 0.0f;
        #pragma unroll
        for (int i = 0; i < 5; i++) {
            s += __expf(v[i] - mx);
            xl += (idx[i] == lbl) ? v[i] : 0.0f;
        }
        #pragma unroll
        for (int off = 1; off < TPR; off <<= 1) {
            s  += __shfl_xor_sync(0xFFFFFFFFu, s, off);
            xl += __shfl_xor_sync(0xFFFFFFFFu, xl, off);
        }

        if (sub == 0) {
            float ce = __logf(s) + mx - xl;
            float df = __ldg(dis + lbl * C_DIM + am) + 0.5f;
            out[1 + row] = df;
            contrib = ce * df;
        }
    }

    // --- block reduction of contrib ---
    __shared__ float sdata[THREADS];
    sdata[tid] = contrib;
    __syncthreads();
    #pragma unroll
    for (int off = THREADS / 2; off > 0; off >>= 1) {
        if (tid < off) sdata[tid] += sdata[tid + off];
        __syncthreads();
    }
    if (tid == 0) {
        atomicAdd(out, sdata[0] * (1.0f / (float)B));
    }
}

extern "C" void kernel_launch(void* const* d_in, const int* in_sizes, int n_in,
                              void* d_out, int out_size) {
    const float* logits = (const float*)d_in[0];
    const int*   labels = (const int*)d_in[1];
    const float* dis    = (const float*)d_in[2];
    float* out = (float*)d_out;

    int B = in_sizes[1];

    init_out_kernel<<<1, 1>>>(out);

    int blocks = (B + ROWS_PER_BLOCK - 1) / ROWS_PER_BLOCK;
    hier_loss_kernel<<<blocks, THREADS>>>(logits, labels, dis, out, B);
}

// round 4
// speedup vs baseline: 1.6896x; 1.6896x over previous
#include <cuda_runtime.h>
#include <cuda_bf16.h>
#include <math.h>

#define C_DIM   40
#define PAD     41                    // 41 mod 32 = 9, gcd(9,32)=1 -> conflict-free columns
#define THREADS 256
#define ROWS    256                   // rows per block == threads per block

__global__ void init_out_kernel(float* out) {
    out[0] = 0.0f;
}

__global__ __launch_bounds__(THREADS) void hier_loss_kernel(
    const float* __restrict__ logits,   // [B, 40]
    const int*   __restrict__ labels,   // [B]
    const float* __restrict__ dis,      // [40, 40]
    float* __restrict__ out,            // out[0]=loss, out[1..B]=distance_factor
    int B)
{
    __shared__ float s[ROWS * PAD];     // 41984 B
    __shared__ float wsum[THREADS / 32];

    const int tid      = threadIdx.x;
    const int blockRow = blockIdx.x * ROWS;

    // ---- stage 256 rows (10240 floats) coalesced via float4 ----
    {
        const float4* src = reinterpret_cast<const float4*>(logits + (long long)blockRow * C_DIM);
        const int nvec = ROWS * C_DIM / 4;   // 2560
        #pragma unroll
        for (int i = tid; i < nvec; i += THREADS) {
            float4 q = __ldg(src + i);
            int base = 4 * i;
            int r0 = base / C_DIM, c0 = base - r0 * C_DIM;
            // 4 consecutive elements; may cross a row boundary
            int i1 = base + 1, i2 = base + 2, i3 = base + 3;
            int r1 = i1 / C_DIM, c1 = i1 - r1 * C_DIM;
            int r2 = i2 / C_DIM, c2 = i2 - r2 * C_DIM;
            int r3 = i3 / C_DIM, c3 = i3 - r3 * C_DIM;
            s[r0 * PAD + c0] = q.x;
            s[r1 * PAD + c1] = q.y;
            s[r2 * PAD + c2] = q.z;
            s[r3 * PAD + c3] = q.w;
        }
    }
    __syncthreads();

    // ---- each thread consumes one row from smem ----
    float contrib = 0.0f;
    const int row = blockRow + tid;
    if (row < B) {
        const float* v = s + tid * PAD;

        // max + argmax (first occurrence)
        float mx = v[0];
        int   am = 0;
        #pragma unroll
        for (int i = 1; i < C_DIM; i++) {
            float x = v[i];
            if (x > mx) { mx = x; am = i; }
        }

        // sum exp(x - max)
        float ssum = 0.0f;
        #pragma unroll
        for (int i = 0; i < C_DIM; i++) {
            ssum += __expf(v[i] - mx);
        }

        int lbl = __ldg(labels + row);
        float ce = __logf(ssum) + mx - v[lbl];

        float df = __ldg(dis + lbl * C_DIM + am) + 0.5f;
        out[1 + row] = df;
        contrib = ce * df;
    }

    // ---- block reduction: warp shuffle, then cross-warp via smem ----
    #pragma unroll
    for (int off = 16; off > 0; off >>= 1)
        contrib += __shfl_xor_sync(0xFFFFFFFFu, contrib, off);

    const int lane = tid & 31;
    const int warp = tid >> 5;
    if (lane == 0) wsum[warp] = contrib;
    __syncthreads();

    if (warp == 0) {
        float t = (lane < THREADS / 32) ? wsum[lane] : 0.0f;
        #pragma unroll
        for (int off = 4; off > 0; off >>= 1)
            t += __shfl_xor_sync(0xFFFFFFFFu, t, off);
        if (lane == 0)
            atomicAdd(out, t * (1.0f / (float)B));
    }
}

extern "C" void kernel_launch(void* const* d_in, const int* in_sizes, int n_in,
                              void* d_out, int out_size) {
    const float* logits = (const float*)d_in[0];
    const int*   labels = (const int*)d_in[1];
    const float* dis    = (const float*)d_in[2];
    float* out = (float*)d_out;

    int B = in_sizes[1];

    init_out_kernel<<<1, 1>>>(out);

    int blocks = (B + ROWS - 1) / ROWS;
    hier_loss_kernel<<<blocks, THREADS>>>(logits, labels, dis, out, B);
}

// round 5
// speedup vs baseline: 1.7678x; 1.0463x over previous
#include <cuda_runtime.h>
#include <cuda_bf16.h>
#include <math.h>

#define C_DIM    40
#define VPR      10                   // float4 vectors per row (data)
#define VPAD     11                   // padded vectors per row -> 44 floats, conflict-free LDS.128
#define THREADS  256
#define ROWS     256                  // rows per block == threads per block

__global__ void init_out_kernel(float* out) {
    out[0] = 0.0f;
}

__global__ __launch_bounds__(THREADS) void hier_loss_kernel(
    const float* __restrict__ logits,   // [B, 40]
    const int*   __restrict__ labels,   // [B]
    const float* __restrict__ dis,      // [40, 40]
    float* __restrict__ out,            // out[0]=loss, out[1..B]=distance_factor
    int B)
{
    __shared__ float4 s4[ROWS * VPAD];  // 256*11*16 = 45056 B
    __shared__ float  wsum[THREADS / 32];

    const int tid      = threadIdx.x;
    const int blockRow = blockIdx.x * ROWS;

    // ---- stage 256 rows coalesced via float4; pad rows 10 -> 11 vecs ----
    {
        const float4* src = reinterpret_cast<const float4*>(logits + (long long)blockRow * C_DIM);
        #pragma unroll
        for (int j = 0; j < ROWS * VPR / THREADS; j++) {       // 10 iterations
            int i = tid + j * THREADS;                          // vector index 0..2559
            float4 q = __ldg(src + i);
            int r = i / VPR;                                    // const-div -> mul/shift
            int c = i - r * VPR;
            s4[r * VPAD + c] = q;
        }
    }
    __syncthreads();

    // ---- each thread consumes one row from smem via 10x LDS.128 ----
    float contrib = 0.0f;
    const int row = blockRow + tid;
    if (row < B) {
        const float4* rowp = s4 + tid * VPAD;

        float v[C_DIM];
        #pragma unroll
        for (int k = 0; k < VPR; k++) {
            float4 q = rowp[k];
            v[4 * k + 0] = q.x;
            v[4 * k + 1] = q.y;
            v[4 * k + 2] = q.z;
            v[4 * k + 3] = q.w;
        }

        // max + argmax (first occurrence)
        float mx = v[0];
        int   am = 0;
        #pragma unroll
        for (int i = 1; i < C_DIM; i++) {
            if (v[i] > mx) { mx = v[i]; am = i; }
        }

        // sum exp(x - max)
        float ssum = 0.0f;
        #pragma unroll
        for (int i = 0; i < C_DIM; i++) {
            ssum += __expf(v[i] - mx);
        }

        int lbl = __ldg(labels + row);
        // x[label] via scalar LDS (avoids dynamic register indexing / spills)
        float xl = reinterpret_cast<const float*>(rowp)[lbl];

        float ce = __logf(ssum) + mx - xl;
        float df = __ldg(dis + lbl * C_DIM + am) + 0.5f;
        out[1 + row] = df;
        contrib = ce * df;
    }

    // ---- block reduction: warp shuffle, then cross-warp via smem ----
    #pragma unroll
    for (int off = 16; off > 0; off >>= 1)
        contrib += __shfl_xor_sync(0xFFFFFFFFu, contrib, off);

    const int lane = tid & 31;
    const int warp = tid >> 5;
    if (lane == 0) wsum[warp] = contrib;
    __syncthreads();

    if (warp == 0) {
        float t = (lane < THREADS / 32) ? wsum[lane] : 0.0f;
        #pragma unroll
        for (int off = 4; off > 0; off >>= 1)
            t += __shfl_xor_sync(0xFFFFFFFFu, t, off);
        if (lane == 0)
            atomicAdd(out, t * (1.0f / (float)B));
    }
}

extern "C" void kernel_launch(void* const* d_in, const int* in_sizes, int n_in,
                              void* d_out, int out_size) {
    const float* logits = (const float*)d_in[0];
    const int*   labels = (const int*)d_in[1];
    const float* dis    = (const float*)d_in[2];
    float* out = (float*)d_out;

    int B = in_sizes[1];

    init_out_kernel<<<1, 1>>>(out);

    int blocks = (B + ROWS - 1) / ROWS;
    hier_loss_kernel<<<blocks, THREADS>>>(logits, labels, dis, out, B);
}